// round 4
// baseline (speedup 1.0000x reference)
#include <cuda_runtime.h>
#include <math.h>
#include <stdint.h>

// Problem constants
#define BB 16
#define NN 4096
#define DD 64
#define OO 12
#define SS 32
#define MM 12
#define AA 32

#define SCALE 0.17677669529663687f   // 1/sqrt(32)
#define TWO_PI 6.283185307179586f
#define ALPHA 0.1f

// Scratch per (b,o): sn[16] | cs[16] | cmb_scaled[16] | valg_alpha[12][64]
#define SN_OFF   0
#define CS_OFF   16
#define CMB_OFF  32
#define VALG_OFF 48
#define PER_BO   816

__device__ float g_scratch[BB * OO * PER_BO];

#define ATTN_OUT_OFF ((size_t)BB*OO*NN*DD)
#define GATE_OUT_OFF (ATTN_OUT_OFF + (size_t)BB*OO*NN*MM)

// Packed dual-FMA (fp32x2) — ptxas never auto-fuses this.
__device__ __forceinline__ float2 ffma2(float2 a, float2 b, float2 c) {
    float2 d;
    asm("{\n"
        ".reg .b64 ra, rb, rc, rd;\n"
        "mov.b64 ra, {%2, %3};\n"
        "mov.b64 rb, {%4, %5};\n"
        "mov.b64 rc, {%6, %7};\n"
        "fma.rn.f32x2 rd, ra, rb, rc;\n"
        "mov.b64 {%0, %1}, rd;\n"
        "}"
        : "=f"(d.x), "=f"(d.y)
        : "f"(a.x), "f"(a.y), "f"(b.x), "f"(b.y), "f"(c.x), "f"(c.y));
    return d;
}

__device__ __forceinline__ void cp_async16(uint32_t dst_smem, const void* src) {
    asm volatile("cp.async.cg.shared.global [%0], [%1], 16;\n" :: "r"(dst_smem), "l"(src));
}
__device__ __forceinline__ void cp_async_commit() { asm volatile("cp.async.commit_group;\n"); }
__device__ __forceinline__ void cp_async_wait_all() { asm volatile("cp.async.wait_group 0;\n" ::: "memory"); }

// ---------------------------------------------------------------------------
// Precompute per-(b,o): sn, cs, cmb*SCALE, ALPHA*gate*val_emb, gate output.
// ---------------------------------------------------------------------------
__global__ void precompute_kernel(const float* __restrict__ ts_out,
                                  const float* __restrict__ step_emb,
                                  const float* __restrict__ key_emb,
                                  const float* __restrict__ val_emb,
                                  const float* __restrict__ Wk,
                                  const float* __restrict__ Wg,
                                  const float* __restrict__ bg,
                                  const float* __restrict__ Wq,
                                  const float* __restrict__ bq,
                                  float* __restrict__ out)
{
    __shared__ float qs_s[AA];
    __shared__ float key_sh[MM * AA];
    __shared__ float gate_sh[MM];

    const int bo = blockIdx.x;
    const int t  = threadIdx.x;
    const float tod = ts_out[bo * 2 + 0];
    const float dow = ts_out[bo * 2 + 1];
    float* dst = g_scratch + (size_t)bo * PER_BO;

    for (int i = t; i < MM * AA; i += 64) {
        int m = i >> 5, a = i & 31;
        float ph = (m < 8) ? tod : dow;
        float kf = (m < 8) ? (float)(m + 1) : (float)(m - 7);
        float sn, cs; sincosf(TWO_PI * ph * kf, &sn, &cs);
        key_sh[i] = sn * Wk[a * 2 + 0] + cs * Wk[a * 2 + 1] + key_emb[i];
    }
    if (t < MM) {
        int m = t;
        float ph = (m < 8) ? tod : dow;
        float kf = (m < 8) ? (float)(m + 1) : (float)(m - 7);
        float sn, cs; sincosf(TWO_PI * ph * kf, &sn, &cs);
        dst[SN_OFF + m] = sn;
        dst[CS_OFF + m] = cs;
        float gv = tanhf(sn * Wg[0] + cs * Wg[1] + bg[0]);
        gate_sh[m] = gv;
        out[GATE_OUT_OFF + (size_t)bo * MM + m] = gv;
    } else if (t < 16) {
        dst[SN_OFF + t] = 0.f; dst[CS_OFF + t] = 0.f; dst[CMB_OFF + t] = 0.f;
    }
    if (t < AA) {
        float acc = bq[t];
        const float* se = step_emb + bo * SS;
        const float* wr = Wq + t * (DD + SS) + DD;
        #pragma unroll 8
        for (int si = 0; si < SS; si++) acc = fmaf(se[si], wr[si], acc);
        qs_s[t] = acc;
    }
    __syncthreads();
    for (int i = t; i < MM * DD; i += 64) {
        int m = i >> 6;
        dst[VALG_OFF + i] = ALPHA * gate_sh[m] * val_emb[i];
    }
    if (t < MM) {
        float acc = 0.f;
        #pragma unroll
        for (int a = 0; a < AA; a++) acc += qs_s[a] * key_sh[t * AA + a];
        dst[CMB_OFF + t] = acc * SCALE;
    }
}

// ---------------------------------------------------------------------------
// Kernel A: attention. Block = (b, 128-row tile), pair of threads per row.
// Writes attn [B,O,N,M] only.
// ---------------------------------------------------------------------------
#define A_TILE 128
#define A_THREADS 256
#define WQT_STRIDE 34

__global__ __launch_bounds__(A_THREADS)
void stta_attn(const float* __restrict__ H, const float* __restrict__ Wq,
               const float* __restrict__ key_emb, const float* __restrict__ Wk,
               float* __restrict__ out)
{
    __shared__ float wqt[DD * WQT_STRIDE];
    __shared__ float ke[MM * AA];
    __shared__ float wk0[32];
    __shared__ float wk1[32];
    __shared__ float buf[2 * 48];

    const int t  = threadIdx.x;
    const int b  = blockIdx.y;
    const int n0 = blockIdx.x * A_TILE;

    // prefetch o=0 params (48 floats)
    if (t < 12) {
        const float* src = g_scratch + (size_t)(b * OO) * PER_BO + t * 4;
        cp_async16((uint32_t)__cvta_generic_to_shared(buf) + (uint32_t)t * 16, src);
    }
    cp_async_commit();

    for (int i = t; i < AA * DD; i += A_THREADS) {
        int a = i >> 6, d = i & 63;
        wqt[d * WQT_STRIDE + a] = Wq[a * (DD + SS) + d];
    }
    for (int i = t; i < MM * AA; i += A_THREADS) ke[i] = key_emb[i];
    if (t < 32) { wk0[t] = Wk[t * 2]; wk1[t] = Wk[t * 2 + 1]; }
    cp_async_wait_all();
    __syncthreads();

    const int r  = t >> 1;
    const int h  = t & 1;
    const int a0 = h * 16;

    float es[MM];
    float p0s, p1s;
    {
        const float4* Hrow4 = (const float4*)(H + ((size_t)b * NN + n0 + r) * DD);
        float2 qh2[8];
        #pragma unroll
        for (int j = 0; j < 8; j++) qh2[j] = make_float2(0.f, 0.f);
        #pragma unroll 4
        for (int d4 = 0; d4 < 16; d4++) {
            float4 hv = Hrow4[d4];
            #pragma unroll
            for (int q = 0; q < 4; q++) {
                float hvq = (q == 0) ? hv.x : (q == 1) ? hv.y : (q == 2) ? hv.z : hv.w;
                float2 hd = make_float2(hvq, hvq);
                const float* wrow = wqt + (4 * d4 + q) * WQT_STRIDE + a0;
                #pragma unroll
                for (int j = 0; j < 8; j++)
                    qh2[j] = ffma2(hd, *(const float2*)(wrow + 2 * j), qh2[j]);
            }
        }
        #pragma unroll
        for (int m = 0; m < MM; m++) {
            float2 acc = make_float2(0.f, 0.f);
            const float* kr = ke + m * AA + a0;
            #pragma unroll
            for (int j = 0; j < 8; j++)
                acc = ffma2(qh2[j], *(const float2*)(kr + 2 * j), acc);
            float p = acc.x + acc.y;
            p += __shfl_xor_sync(0xffffffffu, p, 1);
            es[m] = p * SCALE;
        }
        float2 a0v = make_float2(0.f, 0.f), a1v = make_float2(0.f, 0.f);
        #pragma unroll
        for (int j = 0; j < 8; j++) {
            a0v = ffma2(qh2[j], *(const float2*)(wk0 + a0 + 2 * j), a0v);
            a1v = ffma2(qh2[j], *(const float2*)(wk1 + a0 + 2 * j), a1v);
        }
        float p0 = a0v.x + a0v.y; p0 += __shfl_xor_sync(0xffffffffu, p0, 1);
        float p1 = a1v.x + a1v.y; p1 += __shfl_xor_sync(0xffffffffu, p1, 1);
        p0s = p0 * SCALE; p1s = p1 * SCALE;
    }

    #pragma unroll 1
    for (int o = 0; o < OO; o++) {
        const float* cur = buf + (o & 1) * 48;
        if (o < OO - 1) {
            if (t < 12) {
                const float* src = g_scratch + (size_t)(b * OO + o + 1) * PER_BO + t * 4;
                cp_async16((uint32_t)__cvta_generic_to_shared(buf + ((o + 1) & 1) * 48)
                           + (uint32_t)t * 16, src);
            }
            cp_async_commit();
        }

        float lg[MM];
        #pragma unroll
        for (int m = 0; m < MM; m++)
            lg[m] = fmaf(cur[SN_OFF + m], p0s,
                    fmaf(cur[CS_OFF + m], p1s, es[m] + cur[CMB_OFF + m]));

        float mx = lg[0];
        #pragma unroll
        for (int m = 1; m < MM; m++) mx = fmaxf(mx, lg[m]);
        float sum = 0.f;
        #pragma unroll
        for (int m = 0; m < MM; m++) { lg[m] = __expf(lg[m] - mx); sum += lg[m]; }
        float inv = 1.f / sum;
        #pragma unroll
        for (int m = 0; m < MM; m++) lg[m] *= inv;

        float* ao = out + ATTN_OUT_OFF + (((size_t)(b * OO + o)) * NN + n0 + r) * MM;
        if (h == 0) {
            *(float4*)(ao + 0) = make_float4(lg[0], lg[1], lg[2], lg[3]);
            *(float4*)(ao + 4) = make_float4(lg[4], lg[5], lg[6], lg[7]);
        } else {
            *(float4*)(ao + 8) = make_float4(lg[8], lg[9], lg[10], lg[11]);
        }

        cp_async_wait_all();
        __syncthreads();
    }
}

// ---------------------------------------------------------------------------
// Kernel B: delta + H_time. Block = (b, 256-row tile). 2 blocks/SM -> 128 regs.
// H slice cached in registers across all 12 o. Reads attn back (L2-hot).
// ---------------------------------------------------------------------------
#define B_TILE 256
#define B_THREADS 256

__global__ __launch_bounds__(B_THREADS, 2)
void stta_delta(const float* __restrict__ H, const float* __restrict__ attn_g,
                float* __restrict__ out)
{
    const int t  = threadIdx.x;
    const int b  = blockIdx.y;
    const int n0 = blockIdx.x * B_TILE;
    const int w  = t >> 5;      // warp: 32 rows each
    const int dp = t & 31;      // d-pair: d = 2*dp

    const size_t rowbase = (size_t)b * NN + n0 + w * 32;

    // Cache H slice: 32 rows x 2 d (reused for all 12 o)
    float2 hv[32];
    {
        const float* hp = H + rowbase * DD + 2 * dp;
        #pragma unroll
        for (int i = 0; i < 32; i++)
            hv[i] = *(const float2*)(hp + (size_t)i * DD);
    }

    #pragma unroll 1
    for (int o = 0; o < OO; o++) {
        const size_t bo = (size_t)(b * OO + o);
        // valg (alpha-folded) for this o, own d-pair
        float2 vg[MM];
        {
            const float* sc = g_scratch + bo * PER_BO + VALG_OFF + 2 * dp;
            #pragma unroll
            for (int m = 0; m < MM; m++)
                vg[m] = *(const float2*)(sc + m * DD);
        }
        const float* ag = attn_g + (bo * NN + n0 + w * 32) * MM;
        float* ho = out + (bo * NN + n0 + w * 32) * DD + 2 * dp;

        #pragma unroll 2
        for (int c = 0; c < 8; c++) {
            #pragma unroll
            for (int i = 0; i < 4; i++) {
                const int row = c * 4 + i;
                const float4* ar = (const float4*)(ag + row * MM);  // broadcast
                float4 A0 = ar[0], A1 = ar[1], A2 = ar[2];
                float2 acc = hv[row];
                acc = ffma2(make_float2(A0.x, A0.x), vg[0],  acc);
                acc = ffma2(make_float2(A0.y, A0.y), vg[1],  acc);
                acc = ffma2(make_float2(A0.z, A0.z), vg[2],  acc);
                acc = ffma2(make_float2(A0.w, A0.w), vg[3],  acc);
                acc = ffma2(make_float2(A1.x, A1.x), vg[4],  acc);
                acc = ffma2(make_float2(A1.y, A1.y), vg[5],  acc);
                acc = ffma2(make_float2(A1.z, A1.z), vg[6],  acc);
                acc = ffma2(make_float2(A1.w, A1.w), vg[7],  acc);
                acc = ffma2(make_float2(A2.x, A2.x), vg[8],  acc);
                acc = ffma2(make_float2(A2.y, A2.y), vg[9],  acc);
                acc = ffma2(make_float2(A2.z, A2.z), vg[10], acc);
                acc = ffma2(make_float2(A2.w, A2.w), vg[11], acc);
                *(float2*)(ho + (size_t)row * DD) = acc;
            }
        }
    }
}

extern "C" void kernel_launch(void* const* d_in, const int* in_sizes, int n_in,
                              void* d_out, int out_size)
{
    const float* H        = (const float*)d_in[0];
    const float* ts_out   = (const float*)d_in[1];
    const float* step_emb = (const float*)d_in[2];
    const float* key_emb  = (const float*)d_in[3];
    const float* val_emb  = (const float*)d_in[4];
    const float* Wk       = (const float*)d_in[5];
    const float* Wg       = (const float*)d_in[6];
    const float* bg       = (const float*)d_in[7];
    const float* Wq       = (const float*)d_in[8];
    const float* bq       = (const float*)d_in[9];
    float* out = (float*)d_out;

    precompute_kernel<<<BB * OO, 64>>>(ts_out, step_emb, key_emb, val_emb,
                                       Wk, Wg, bg, Wq, bq, out);

    dim3 gridA(NN / A_TILE, BB);
    stta_attn<<<gridA, A_THREADS>>>(H, Wq, key_emb, Wk, out);

    dim3 gridB(NN / B_TILE, BB);
    stta_delta<<<gridB, B_THREADS>>>(H, out + ATTN_OUT_OFF, out);
}